// round 12
// baseline (speedup 1.0000x reference)
#include <cuda_runtime.h>
#include <cuda_fp16.h>
#include <cstdint>

#define Bq   8
#define Nn   1024
#define DIN  256
#define DOUT 256
#define Rr   4

// ------------------------- scratch globals ----------------------------------
__device__ __half    g_xf[(size_t)Bq * Nn * DIN];
__device__ __half    g_rwhf[(size_t)Rr * DOUT * DIN];
__device__ __half    g_rwlf[(size_t)Rr * DOUT * DIN];
__device__ float     g_w[Bq * Rr * Nn];
__device__ float     g_invZ[Bq * Rr * Nn];
__device__ __half    g_wff[(size_t)Bq * Rr * DOUT * Nn];   // wf^T fp16 [br][d][m]
__device__ uint32_t  g_bits[(size_t)Bq * Rr * Nn * 32];    // 4 MB packed adj

// ------------------------- helpers ------------------------------------------
__device__ __forceinline__ uint32_t smem_u32(const void* p) {
    uint32_t a;
    asm("{ .reg .u64 t; cvta.to.shared.u64 t, %1; cvt.u32.u64 %0, t; }"
        : "=r"(a) : "l"(p));
    return a;
}
#define CP_ASYNC16(dst, src) asm volatile("cp.async.cg.shared.global [%0], [%1], 16;" :: "r"(dst), "l"(src))
#define CP_ASYNC8(dst, src)  asm volatile("cp.async.ca.shared.global [%0], [%1], 8;"  :: "r"(dst), "l"(src))
#define CP_COMMIT()          asm volatile("cp.async.commit_group;" ::: "memory")
#define CP_WAIT1()           asm volatile("cp.async.wait_group 1;" ::: "memory")
#define CP_WAIT0()           asm volatile("cp.async.wait_group 0;" ::: "memory")

__device__ __forceinline__ uint32_t sw128(uint32_t off) {
    return off ^ ((off >> 3) & 0x70);
}
__device__ __forceinline__ void ldsm4(uint32_t& r0, uint32_t& r1,
                                      uint32_t& r2, uint32_t& r3, uint32_t a) {
    asm volatile("ldmatrix.sync.aligned.m8n8.x4.shared.b16 {%0,%1,%2,%3}, [%4];"
                 : "=r"(r0), "=r"(r1), "=r"(r2), "=r"(r3) : "r"(a));
}
__device__ __forceinline__ void mma16816h(float* c, const uint32_t* a,
                                          const uint32_t* b) {
    asm volatile("mma.sync.aligned.m16n8k16.row.col.f32.f16.f16.f32 "
        "{%0,%1,%2,%3}, {%4,%5,%6,%7}, {%8,%9}, {%0,%1,%2,%3};"
        : "+f"(c[0]), "+f"(c[1]), "+f"(c[2]), "+f"(c[3])
        : "r"(a[0]), "r"(a[1]), "r"(a[2]), "r"(a[3]), "r"(b[0]), "r"(b[1]));
}
__device__ __forceinline__ void hsplit(float v, __half& h, __half& l) {
    h = __float2half_rn(v);
    l = __float2half_rn(v - __half2float(h));
}
__device__ __forceinline__ uint32_t pack_h2(__half a, __half b) {
    return (uint32_t)__half_as_ushort(a) | ((uint32_t)__half_as_ushort(b) << 16);
}
// spread 8 bits to every 4th position (bit i -> bit 4i)
__device__ __forceinline__ uint32_t spread4(uint32_t x) {
    x = (x | (x << 12)) & 0x000F000Fu;
    x = (x | (x << 6))  & 0x03030303u;
    x = (x | (x << 3))  & 0x11111111u;
    return x;
}
// 2 adjacency bits -> packed fp16x2 {0,1}
__device__ __forceinline__ uint32_t pk2(uint32_t bb) {
    return ((bb & 1u) ? 0x3C00u : 0u) | ((bb & 2u) ? 0x3C000000u : 0u);
}

// ---------------------------------------------------------------------------
// conversions
// ---------------------------------------------------------------------------
__global__ __launch_bounds__(256) void conv_x_kernel(const float* __restrict__ x) {
    size_t i = (size_t)blockIdx.x * 256 + threadIdx.x;
    float4 v = ((const float4*)x)[i];
    uint2 H;
    H.x = pack_h2(__float2half_rn(v.x), __float2half_rn(v.y));
    H.y = pack_h2(__float2half_rn(v.z), __float2half_rn(v.w));
    *(uint2*)&g_xf[4 * i] = H;
}
__global__ __launch_bounds__(256) void conv_rw_kernel(const float* __restrict__ rw) {
    size_t i = (size_t)blockIdx.x * 256 + threadIdx.x;
    float4 v = ((const float4*)rw)[i];
    __half h0, h1, h2, h3, l0, l1, l2, l3;
    hsplit(v.x, h0, l0); hsplit(v.y, h1, l1);
    hsplit(v.z, h2, l2); hsplit(v.w, h3, l3);
    uint2 H, L;
    H.x = pack_h2(h0, h1); H.y = pack_h2(h2, h3);
    L.x = pack_h2(l0, l1); L.y = pack_h2(l2, l3);
    *(uint2*)&g_rwhf[4 * i] = H;
    *(uint2*)&g_rwlf[4 * i] = L;
}

// ---------------------------------------------------------------------------
// FUSED feats+wf kernel (2-term fp16: x single, rw hi/lo)  [unchanged R8]
// ---------------------------------------------------------------------------
#define FW_SMEM (1024 + 2 * 81920)
__global__ __launch_bounds__(512, 1) void fw_kernel(
    const float* __restrict__ rb, const float* __restrict__ aw)
{
    extern __shared__ char smem[];
    __shared__ float awjs[256];
    __shared__ float rbs[256];
    __shared__ float sjred[4][128];
    __shared__ float wsm[128];
    char* abp = (char*)(((uintptr_t)smem + 1023) & ~(uintptr_t)1023);
    const uint32_t ab = (smem_u32(smem) + 1023) & ~1023u;
    const int tid = threadIdx.x, wid = tid >> 5, lane = tid & 31;
    const int n0 = blockIdx.x * 128;
    const int br = blockIdx.y, b = br >> 2, r = br & 3;
    const int wm = (wid >> 2) * 32, wn = (wid & 3) * 64;

    if (tid < 256) { awjs[tid] = aw[DOUT + tid]; rbs[tid] = rb[r * DOUT + tid]; }

    auto prefetch = [&](int c, int stage) {
        uint32_t base = ab + stage * 81920;
        for (int u = tid; u < 5120; u += 512) {
            uint32_t dst;
            const __half* src;
            if (u < 1024) {
                int row = u >> 3, un = u & 7;
                dst = base + sw128(row * 128 + un * 16);
                src = g_xf + (size_t)b * (Nn * DIN) + (size_t)(n0 + row) * DIN
                    + c * 64 + un * 8;
            } else {
                int v2 = u - 1024;
                int t = v2 >> 11, v = v2 & 2047, row = v >> 3, un = v & 7;
                dst = base + 16384 + t * 32768 + sw128(row * 128 + un * 16);
                src = (t ? g_rwlf : g_rwhf)
                    + (size_t)r * (DOUT * DIN) + (size_t)row * DIN + c * 64 + un * 8;
            }
            CP_ASYNC16(dst, (const char*)src);
        }
        CP_COMMIT();
    };

    float acc[2][8][4] = {};
    const int grp = lane >> 3, l7 = lane & 7;
    const int arow = (grp & 1) * 8 + l7, ac16 = (grp >> 1) * 16;
    const int brow = (grp >> 1) * 8 + l7, bc16 = (grp & 1) * 16;

    prefetch(0, 0);
    for (int c = 0; c < 4; c++) {
        if (c + 1 < 4) { prefetch(c + 1, (c + 1) & 1); CP_WAIT1(); }
        else           { CP_WAIT0(); }
        __syncthreads();
        uint32_t base = ab + (c & 1) * 81920;
        #pragma unroll
        for (int ks = 0; ks < 4; ks++) {
            int kb = ks * 32;
            uint32_t Ax[2][4];
            #pragma unroll
            for (int mf = 0; mf < 2; mf++) {
                uint32_t off = sw128((wm + mf * 16 + arow) * 128 + kb + ac16);
                ldsm4(Ax[mf][0], Ax[mf][1], Ax[mf][2], Ax[mf][3], base + off);
            }
            #pragma unroll
            for (int g = 0; g < 4; g++) {
                uint32_t off = sw128((wn + g * 16 + brow) * 128 + kb + bc16);
                uint32_t h0, h1, h2, h3, q0, q1, q2, q3;
                ldsm4(h0, h1, h2, h3, base + 16384 + off);
                ldsm4(q0, q1, q2, q3, base + 49152 + off);
                uint32_t Bh0[2] = {h0, h1}, Bh1[2] = {h2, h3};
                uint32_t Bl0[2] = {q0, q1}, Bl1[2] = {q2, q3};
                #pragma unroll
                for (int mf = 0; mf < 2; mf++) {
                    mma16816h(acc[mf][2*g],   Ax[mf], Bh0);
                    mma16816h(acc[mf][2*g+1], Ax[mf], Bh1);
                    mma16816h(acc[mf][2*g],   Ax[mf], Bl0);
                    mma16816h(acc[mf][2*g+1], Ax[mf], Bl1);
                }
            }
        }
        __syncthreads();
    }

    #pragma unroll
    for (int nf = 0; nf < 8; nf++) {
        int c0 = wn + nf * 8 + 2 * (lane & 3);
        float b0 = rbs[c0], b1 = rbs[c0 + 1];
        #pragma unroll
        for (int mf = 0; mf < 2; mf++) {
            acc[mf][nf][0] += b0; acc[mf][nf][1] += b1;
            acc[mf][nf][2] += b0; acc[mf][nf][3] += b1;
        }
    }

    float p[2][2] = {};
    #pragma unroll
    for (int nf = 0; nf < 8; nf++) {
        int c0 = wn + nf * 8 + 2 * (lane & 3);
        float a0 = awjs[c0], a1 = awjs[c0 + 1];
        #pragma unroll
        for (int mf = 0; mf < 2; mf++) {
            p[mf][0] = fmaf(acc[mf][nf][0], a0, fmaf(acc[mf][nf][1], a1, p[mf][0]));
            p[mf][1] = fmaf(acc[mf][nf][2], a0, fmaf(acc[mf][nf][3], a1, p[mf][1]));
        }
    }
    #pragma unroll
    for (int mf = 0; mf < 2; mf++)
        #pragma unroll
        for (int q = 0; q < 2; q++) {
            p[mf][q] += __shfl_xor_sync(0xffffffffu, p[mf][q], 1);
            p[mf][q] += __shfl_xor_sync(0xffffffffu, p[mf][q], 2);
            if ((lane & 3) == 0)
                sjred[wid & 3][wm + mf * 16 + q * 8 + (lane >> 2)] = p[mf][q];
        }
    __syncthreads();

    if (tid < 128) {
        float s = sjred[0][tid] + sjred[1][tid] + sjred[2][tid] + sjred[3][tid];
        float w = __expf(s);
        wsm[tid] = w;
        g_w[br * Nn + n0 + tid] = w;
    }
    __syncthreads();

    __half* thf = (__half*)abp;
    #pragma unroll
    for (int mf = 0; mf < 2; mf++)
        #pragma unroll
        for (int q = 0; q < 2; q++) {
            int row = wm + mf * 16 + q * 8 + (lane >> 2);
            float w = wsm[row];
            #pragma unroll
            for (int nf = 0; nf < 8; nf++) {
                int c0 = wn + nf * 8 + 2 * (lane & 3);
                thf[c0 * 128 + row]       = __float2half(acc[mf][nf][2 * q] * w);
                thf[(c0 + 1) * 128 + row] = __float2half(acc[mf][nf][2 * q + 1] * w);
            }
        }
    __syncthreads();

    for (int it = 0; it < 4; it++) {
        int idx = it * 512 + tid;
        int d = idx >> 3, mq = idx & 7;
        size_t go = ((size_t)br * DOUT + d) * Nn + n0 + mq * 16;
        *(uint4*)&g_wff[go]     = *(uint4*)&thf[d * 128 + mq * 16];
        *(uint4*)&g_wff[go + 8] = *(uint4*)&thf[d * 128 + mq * 16 + 8];
    }
}

// ---------------------------------------------------------------------------
// prepass: adj int32 -> packed bits (1b/elem); invZ[br,n] = 1/sum_m adj*w
// ---------------------------------------------------------------------------
__global__ __launch_bounds__(256) void prepass_kernel(const int* __restrict__ adj) {
    __shared__ float ws[Nn];
    const int tid = threadIdx.x, wid = tid >> 5, lane = tid & 31;
    const int br = blockIdx.x >> 5, nb = blockIdx.x & 31;
    for (int i = tid; i < Nn; i += 256) ws[i] = g_w[br * Nn + i];
    __syncthreads();

    #pragma unroll
    for (int i = 0; i < 4; i++) {
        int n = nb * 32 + wid * 4 + i;
        const int4* arow = (const int4*)(adj + (((size_t)br << 10) + n) * Nn);
        uint32_t* bout = g_bits + (((size_t)br << 10) + n) * 32;
        float z = 0.f;
        #pragma unroll
        for (int k = 0; k < 8; k++) {
            int m = k * 128 + lane * 4;
            int4 a = arow[k * 32 + lane];
            uint32_t b0 = __ballot_sync(0xffffffffu, a.x != 0);
            uint32_t b1 = __ballot_sync(0xffffffffu, a.y != 0);
            uint32_t b2 = __ballot_sync(0xffffffffu, a.z != 0);
            uint32_t b3 = __ballot_sync(0xffffffffu, a.w != 0);
            if (lane < 4) {
                uint32_t w = spread4((b0 >> (8 * lane)) & 0xFFu)
                           | (spread4((b1 >> (8 * lane)) & 0xFFu) << 1)
                           | (spread4((b2 >> (8 * lane)) & 0xFFu) << 2)
                           | (spread4((b3 >> (8 * lane)) & 0xFFu) << 3);
                bout[k * 4 + lane] = w;
            }
            if (a.x) z += ws[m];
            if (a.y) z += ws[m + 1];
            if (a.z) z += ws[m + 2];
            if (a.w) z += ws[m + 3];
        }
        #pragma unroll
        for (int o = 16; o; o >>= 1) z += __shfl_xor_sync(0xffffffffu, z, o);
        if (lane == 0) g_invZ[(br << 10) + n] = 1.0f / z;
    }
}

// ---------------------------------------------------------------------------
// agg via fp16 mma.sync; A tile expanded in-smem from packed adjacency bits.
//   out[b,n,d] = sum_r invZ[r,n] * (adj_r @ wf_r^T)[n,d]
// CTA tile 64n x 128d; 32 super-chunks of K=128 (2 sub-chunks of 64).
// 8 warps 2x4, warp tile 32n x 32d. grid (2, 16, 8) = 256 CTAs, 2 CTA/SM.
// sub-chunk stage: Af 8KB | Bf 16KB | bits 0.5KB (pad) = 25KB; super 50KB x2.
// NOTE: trailing __syncthreads() after MMA is load-bearing (R10's missing
// sync let prefetch(sc+2) overwrite stage (sc&1) under lagging ldsm reads).
// ---------------------------------------------------------------------------
#define SUBST  25600
#define SUPST  51200
#define A_SMEM (1024 + 2 * SUPST)
__global__ __launch_bounds__(256, 2) void agg_mma_kernel(float* __restrict__ out) {
    extern __shared__ char smem[];
    __shared__ float izs[Rr * 64];
    char* abp = (char*)(((uintptr_t)smem + 1023) & ~(uintptr_t)1023);
    const uint32_t ab = (smem_u32(smem) + 1023) & ~1023u;
    const int tid = threadIdx.x, wid = tid >> 5, lane = tid & 31;
    const int d0 = blockIdx.x * 128;
    const int n0 = blockIdx.y * 64;
    const int b  = blockIdx.z;
    const int wm = (wid >> 2) * 32, wn = (wid & 3) * 32;

    if (tid < Rr * 64)
        izs[tid] = g_invZ[((b * Rr + (tid >> 6)) << 10) + n0 + (tid & 63)];

    auto prefetch = [&](int sc, int stage) {
        uint32_t sbase = ab + stage * SUPST;
        #pragma unroll
        for (int cc = 0; cc < 2; cc++) {
            int c = sc * 2 + cc;
            int r = c >> 4, kc = c & 15, m0 = kc * 64;
            uint32_t base = sbase + cc * SUBST;
            size_t brr = (size_t)(b * Rr + r);
            for (int u = tid; u < 1024; u += 256) {     // B: 128 d x 64 m fp16
                int row = u >> 3, un = u & 7;
                uint32_t dst = base + 8192 + sw128(row * 128 + un * 16);
                const __half* src = g_wff + (brr * DOUT + d0 + row) * Nn + m0 + un * 8;
                CP_ASYNC16(dst, (const char*)src);
            }
            if (tid < 64) {                             // bits: 64 rows x 8 B
                uint32_t dst = base + 24576 + tid * 8;
                const uint32_t* src = g_bits + (brr * Nn + n0 + tid) * 32 + kc * 2;
                CP_ASYNC8(dst, (const char*)src);
            }
        }
        CP_COMMIT();
    };

    float total[2][4][4] = {};
    float acc[2][4][4] = {};
    const int grp = lane >> 3, l7 = lane & 7;
    const int arow = (grp & 1) * 8 + l7, ac16 = (grp >> 1) * 16;
    const int brow = (grp >> 1) * 8 + l7, bc16 = (grp & 1) * 16;
    const int crow = tid >> 2, cseg = tid & 3;   // expansion: row, 16-m segment
    const int SC = 32;

    prefetch(0, 0);
    for (int sc = 0; sc < SC; sc++) {
        if (sc + 1 < SC) { prefetch(sc + 1, (sc + 1) & 1); CP_WAIT1(); }
        else             { CP_WAIT0(); }
        __syncthreads();

        // ---- expand bits -> Af fp16 {0,1} for both sub-chunks ---------------
        char* sb = abp + (sc & 1) * SUPST;
        #pragma unroll
        for (int cc = 0; cc < 2; cc++) {
            char* cbase = sb + cc * SUBST;
            uint32_t word = *(const uint32_t*)(cbase + 24576 + crow * 8 + (cseg >> 1) * 4);
            uint32_t bits = (cseg & 1) ? (word >> 16) : (word & 0xFFFFu);
            uint4 o;
            o.x = pk2(bits);       o.y = pk2(bits >> 2);
            o.z = pk2(bits >> 4);  o.w = pk2(bits >> 6);
            *(uint4*)(cbase + sw128(crow * 128 + cseg * 32)) = o;
            o.x = pk2(bits >> 8);  o.y = pk2(bits >> 10);
            o.z = pk2(bits >> 12); o.w = pk2(bits >> 14);
            *(uint4*)(cbase + sw128(crow * 128 + cseg * 32 + 16)) = o;
        }
        __syncthreads();

        // ---- MMA both sub-chunks --------------------------------------------
        uint32_t sbase = ab + (sc & 1) * SUPST;
        #pragma unroll
        for (int cc = 0; cc < 2; cc++) {
            uint32_t base = sbase + cc * SUBST;
            #pragma unroll
            for (int ks = 0; ks < 4; ks++) {
                int kb = ks * 32;
                uint32_t A[2][4], Bf4[4][2];
                #pragma unroll
                for (int mf = 0; mf < 2; mf++) {
                    uint32_t off = sw128((wm + mf * 16 + arow) * 128 + kb + ac16);
                    ldsm4(A[mf][0], A[mf][1], A[mf][2], A[mf][3], base + off);
                }
                #pragma unroll
                for (int g = 0; g < 2; g++) {
                    uint32_t off = sw128((wn + g * 16 + brow) * 128 + kb + bc16);
                    uint32_t t0, t1, t2, t3;
                    ldsm4(t0, t1, t2, t3, base + 8192 + off);
                    Bf4[2*g][0] = t0; Bf4[2*g][1] = t1;
                    Bf4[2*g+1][0] = t2; Bf4[2*g+1][1] = t3;
                }
                #pragma unroll
                for (int mf = 0; mf < 2; mf++)
                    #pragma unroll
                    for (int nf = 0; nf < 4; nf++)
                        mma16816h(acc[mf][nf], A[mf], Bf4[nf]);
            }
        }
        __syncthreads();     // REQUIRED: protects stage (sc&1) from prefetch(sc+2)

        if ((sc & 7) == 7) {             // end of relation r: fold with invZ
            int r = sc >> 3;
            #pragma unroll
            for (int mf = 0; mf < 2; mf++) {
                float iz0 = izs[r * 64 + wm + mf * 16 + (lane >> 2)];
                float iz1 = izs[r * 64 + wm + mf * 16 + (lane >> 2) + 8];
                #pragma unroll
                for (int nf = 0; nf < 4; nf++) {
                    total[mf][nf][0] = fmaf(iz0, acc[mf][nf][0], total[mf][nf][0]);
                    total[mf][nf][1] = fmaf(iz0, acc[mf][nf][1], total[mf][nf][1]);
                    total[mf][nf][2] = fmaf(iz1, acc[mf][nf][2], total[mf][nf][2]);
                    total[mf][nf][3] = fmaf(iz1, acc[mf][nf][3], total[mf][nf][3]);
                    acc[mf][nf][0] = 0.f; acc[mf][nf][1] = 0.f;
                    acc[mf][nf][2] = 0.f; acc[mf][nf][3] = 0.f;
                }
            }
        }
    }

    #pragma unroll
    for (int nf = 0; nf < 4; nf++) {
        int col = d0 + wn + nf * 8 + 2 * (lane & 3);
        #pragma unroll
        for (int mf = 0; mf < 2; mf++) {
            int row = n0 + wm + mf * 16 + (lane >> 2);
            float* p0 = out + ((size_t)b * Nn + row) * DOUT + col;
            float* p1 = out + ((size_t)b * Nn + row + 8) * DOUT + col;
            p0[0] = total[mf][nf][0]; p0[1] = total[mf][nf][1];
            p1[0] = total[mf][nf][2]; p1[1] = total[mf][nf][3];
        }
    }
}

// ---------------------------------------------------------------------------
// gate epilogue: out = sigmoid(out . gw + gb) * out, one block per (b,n)
// ---------------------------------------------------------------------------
__global__ __launch_bounds__(256) void gate_kernel(
    float* __restrict__ out, const float* __restrict__ gw,
    const float* __restrict__ gb_p)
{
    __shared__ float red[8];
    float* o = out + (size_t)blockIdx.x * DOUT;
    int t = threadIdx.x, lane = t & 31;
    float a = o[t];
    float v = a * gw[t];
    #pragma unroll
    for (int off = 16; off; off >>= 1) v += __shfl_xor_sync(0xffffffffu, v, off);
    if (lane == 0) red[t >> 5] = v;
    __syncthreads();
    if (t < 32) {
        float r = (t < 8) ? red[t] : 0.0f;
        #pragma unroll
        for (int off = 4; off; off >>= 1) r += __shfl_xor_sync(0xffffffffu, r, off);
        if (t == 0) red[0] = r;
    }
    __syncthreads();
    float g = 1.0f / (1.0f + __expf(-(red[0] + gb_p[0])));
    o[t] = g * a;
}

// ---------------------------------------------------------------------------
extern "C" void kernel_launch(void* const* d_in, const int* in_sizes, int n_in,
                              void* d_out, int out_size)
{
    const float* x   = (const float*)d_in[0];
    const int*   adj = (const int*)  d_in[1];
    const float* rw  = (const float*)d_in[2];
    const float* rb  = (const float*)d_in[3];
    const float* aw  = (const float*)d_in[4];
    const float* gw  = (const float*)d_in[6];
    const float* gb  = (const float*)d_in[7];
    float* out = (float*)d_out;

    static bool init_done = false;
    if (!init_done) {
        cudaFuncSetAttribute(fw_kernel,
                             cudaFuncAttributeMaxDynamicSharedMemorySize, FW_SMEM);
        cudaFuncSetAttribute(agg_mma_kernel,
                             cudaFuncAttributeMaxDynamicSharedMemorySize, A_SMEM);
        init_done = true;
    }

    conv_x_kernel<<<(Bq * Nn * DIN / 4) / 256, 256>>>(x);
    conv_rw_kernel<<<(Rr * DOUT * DIN / 4) / 256, 256>>>(rw);

    fw_kernel<<<dim3(8, Bq * Rr), 512, FW_SMEM>>>(rb, aw);

    prepass_kernel<<<Bq * Rr * 32, 256>>>(adj);

    agg_mma_kernel<<<dim3(2, 16, Bq), 256, A_SMEM>>>(out);

    gate_kernel<<<Bq * Nn, 256>>>(out, gw, gb);
}

// round 13
// speedup vs baseline: 1.4835x; 1.4835x over previous
#include <cuda_runtime.h>
#include <cuda_fp16.h>
#include <cstdint>

#define Bq   8
#define Nn   1024
#define DIN  256
#define DOUT 256
#define Rr   4

// ------------------------- scratch globals ----------------------------------
__device__ __half g_xf[(size_t)Bq * Nn * DIN];
__device__ __half g_rwhf[(size_t)Rr * DOUT * DIN];
__device__ __half g_rwlf[(size_t)Rr * DOUT * DIN];
__device__ float  g_w[Bq * Rr * Nn];
__device__ float  g_invZ[Bq * Rr * Nn];
__device__ __half g_wff[(size_t)Bq * Rr * DOUT * Nn];      // wf^T fp16 [br][d][m]
__device__ __half g_adjh[(size_t)Bq * Rr * Nn * Nn];       // 64 MB fp16 {0,1}

// ------------------------- helpers ------------------------------------------
__device__ __forceinline__ uint32_t smem_u32(const void* p) {
    uint32_t a;
    asm("{ .reg .u64 t; cvta.to.shared.u64 t, %1; cvt.u32.u64 %0, t; }"
        : "=r"(a) : "l"(p));
    return a;
}
#define CP_ASYNC16(dst, src) asm volatile("cp.async.cg.shared.global [%0], [%1], 16;" :: "r"(dst), "l"(src))
#define CP_COMMIT()          asm volatile("cp.async.commit_group;" ::: "memory")
#define CP_WAIT1()           asm volatile("cp.async.wait_group 1;" ::: "memory")
#define CP_WAIT0()           asm volatile("cp.async.wait_group 0;" ::: "memory")

__device__ __forceinline__ uint32_t sw128(uint32_t off) {
    return off ^ ((off >> 3) & 0x70);
}
__device__ __forceinline__ void ldsm4(uint32_t& r0, uint32_t& r1,
                                      uint32_t& r2, uint32_t& r3, uint32_t a) {
    asm volatile("ldmatrix.sync.aligned.m8n8.x4.shared.b16 {%0,%1,%2,%3}, [%4];"
                 : "=r"(r0), "=r"(r1), "=r"(r2), "=r"(r3) : "r"(a));
}
__device__ __forceinline__ void mma16816h(float* c, const uint32_t* a,
                                          const uint32_t* b) {
    asm volatile("mma.sync.aligned.m16n8k16.row.col.f32.f16.f16.f32 "
        "{%0,%1,%2,%3}, {%4,%5,%6,%7}, {%8,%9}, {%0,%1,%2,%3};"
        : "+f"(c[0]), "+f"(c[1]), "+f"(c[2]), "+f"(c[3])
        : "r"(a[0]), "r"(a[1]), "r"(a[2]), "r"(a[3]), "r"(b[0]), "r"(b[1]));
}
__device__ __forceinline__ void hsplit(float v, __half& h, __half& l) {
    h = __float2half_rn(v);
    l = __float2half_rn(v - __half2float(h));
}
__device__ __forceinline__ uint32_t pack_h2(__half a, __half b) {
    return (uint32_t)__half_as_ushort(a) | ((uint32_t)__half_as_ushort(b) << 16);
}

// ---------------------------------------------------------------------------
// conversions
// ---------------------------------------------------------------------------
__global__ __launch_bounds__(256) void conv_x_kernel(const float* __restrict__ x) {
    size_t i = (size_t)blockIdx.x * 256 + threadIdx.x;
    float4 v = ((const float4*)x)[i];
    uint2 H;
    H.x = pack_h2(__float2half_rn(v.x), __float2half_rn(v.y));
    H.y = pack_h2(__float2half_rn(v.z), __float2half_rn(v.w));
    *(uint2*)&g_xf[4 * i] = H;
}
__global__ __launch_bounds__(256) void conv_rw_kernel(const float* __restrict__ rw) {
    size_t i = (size_t)blockIdx.x * 256 + threadIdx.x;
    float4 v = ((const float4*)rw)[i];
    __half h0, h1, h2, h3, l0, l1, l2, l3;
    hsplit(v.x, h0, l0); hsplit(v.y, h1, l1);
    hsplit(v.z, h2, l2); hsplit(v.w, h3, l3);
    uint2 H, L;
    H.x = pack_h2(h0, h1); H.y = pack_h2(h2, h3);
    L.x = pack_h2(l0, l1); L.y = pack_h2(l2, l3);
    *(uint2*)&g_rwhf[4 * i] = H;
    *(uint2*)&g_rwlf[4 * i] = L;
}

// ---------------------------------------------------------------------------
// FUSED feats+wf kernel (2-term fp16: x single, rw hi/lo)  [unchanged R8]
// ---------------------------------------------------------------------------
#define FW_SMEM (1024 + 2 * 81920)
__global__ __launch_bounds__(512, 1) void fw_kernel(
    const float* __restrict__ rb, const float* __restrict__ aw)
{
    extern __shared__ char smem[];
    __shared__ float awjs[256];
    __shared__ float rbs[256];
    __shared__ float sjred[4][128];
    __shared__ float wsm[128];
    char* abp = (char*)(((uintptr_t)smem + 1023) & ~(uintptr_t)1023);
    const uint32_t ab = (smem_u32(smem) + 1023) & ~1023u;
    const int tid = threadIdx.x, wid = tid >> 5, lane = tid & 31;
    const int n0 = blockIdx.x * 128;
    const int br = blockIdx.y, b = br >> 2, r = br & 3;
    const int wm = (wid >> 2) * 32, wn = (wid & 3) * 64;

    if (tid < 256) { awjs[tid] = aw[DOUT + tid]; rbs[tid] = rb[r * DOUT + tid]; }

    auto prefetch = [&](int c, int stage) {
        uint32_t base = ab + stage * 81920;
        for (int u = tid; u < 5120; u += 512) {
            uint32_t dst;
            const __half* src;
            if (u < 1024) {
                int row = u >> 3, un = u & 7;
                dst = base + sw128(row * 128 + un * 16);
                src = g_xf + (size_t)b * (Nn * DIN) + (size_t)(n0 + row) * DIN
                    + c * 64 + un * 8;
            } else {
                int v2 = u - 1024;
                int t = v2 >> 11, v = v2 & 2047, row = v >> 3, un = v & 7;
                dst = base + 16384 + t * 32768 + sw128(row * 128 + un * 16);
                src = (t ? g_rwlf : g_rwhf)
                    + (size_t)r * (DOUT * DIN) + (size_t)row * DIN + c * 64 + un * 8;
            }
            CP_ASYNC16(dst, (const char*)src);
        }
        CP_COMMIT();
    };

    float acc[2][8][4] = {};
    const int grp = lane >> 3, l7 = lane & 7;
    const int arow = (grp & 1) * 8 + l7, ac16 = (grp >> 1) * 16;
    const int brow = (grp >> 1) * 8 + l7, bc16 = (grp & 1) * 16;

    prefetch(0, 0);
    for (int c = 0; c < 4; c++) {
        if (c + 1 < 4) { prefetch(c + 1, (c + 1) & 1); CP_WAIT1(); }
        else           { CP_WAIT0(); }
        __syncthreads();
        uint32_t base = ab + (c & 1) * 81920;
        #pragma unroll
        for (int ks = 0; ks < 4; ks++) {
            int kb = ks * 32;
            uint32_t Ax[2][4];
            #pragma unroll
            for (int mf = 0; mf < 2; mf++) {
                uint32_t off = sw128((wm + mf * 16 + arow) * 128 + kb + ac16);
                ldsm4(Ax[mf][0], Ax[mf][1], Ax[mf][2], Ax[mf][3], base + off);
            }
            #pragma unroll
            for (int g = 0; g < 4; g++) {
                uint32_t off = sw128((wn + g * 16 + brow) * 128 + kb + bc16);
                uint32_t h0, h1, h2, h3, q0, q1, q2, q3;
                ldsm4(h0, h1, h2, h3, base + 16384 + off);
                ldsm4(q0, q1, q2, q3, base + 49152 + off);
                uint32_t Bh0[2] = {h0, h1}, Bh1[2] = {h2, h3};
                uint32_t Bl0[2] = {q0, q1}, Bl1[2] = {q2, q3};
                #pragma unroll
                for (int mf = 0; mf < 2; mf++) {
                    mma16816h(acc[mf][2*g],   Ax[mf], Bh0);
                    mma16816h(acc[mf][2*g+1], Ax[mf], Bh1);
                    mma16816h(acc[mf][2*g],   Ax[mf], Bl0);
                    mma16816h(acc[mf][2*g+1], Ax[mf], Bl1);
                }
            }
        }
        __syncthreads();
    }

    #pragma unroll
    for (int nf = 0; nf < 8; nf++) {
        int c0 = wn + nf * 8 + 2 * (lane & 3);
        float b0 = rbs[c0], b1 = rbs[c0 + 1];
        #pragma unroll
        for (int mf = 0; mf < 2; mf++) {
            acc[mf][nf][0] += b0; acc[mf][nf][1] += b1;
            acc[mf][nf][2] += b0; acc[mf][nf][3] += b1;
        }
    }

    float p[2][2] = {};
    #pragma unroll
    for (int nf = 0; nf < 8; nf++) {
        int c0 = wn + nf * 8 + 2 * (lane & 3);
        float a0 = awjs[c0], a1 = awjs[c0 + 1];
        #pragma unroll
        for (int mf = 0; mf < 2; mf++) {
            p[mf][0] = fmaf(acc[mf][nf][0], a0, fmaf(acc[mf][nf][1], a1, p[mf][0]));
            p[mf][1] = fmaf(acc[mf][nf][2], a0, fmaf(acc[mf][nf][3], a1, p[mf][1]));
        }
    }
    #pragma unroll
    for (int mf = 0; mf < 2; mf++)
        #pragma unroll
        for (int q = 0; q < 2; q++) {
            p[mf][q] += __shfl_xor_sync(0xffffffffu, p[mf][q], 1);
            p[mf][q] += __shfl_xor_sync(0xffffffffu, p[mf][q], 2);
            if ((lane & 3) == 0)
                sjred[wid & 3][wm + mf * 16 + q * 8 + (lane >> 2)] = p[mf][q];
        }
    __syncthreads();

    if (tid < 128) {
        float s = sjred[0][tid] + sjred[1][tid] + sjred[2][tid] + sjred[3][tid];
        float w = __expf(s);
        wsm[tid] = w;
        g_w[br * Nn + n0 + tid] = w;
    }
    __syncthreads();

    __half* thf = (__half*)abp;
    #pragma unroll
    for (int mf = 0; mf < 2; mf++)
        #pragma unroll
        for (int q = 0; q < 2; q++) {
            int row = wm + mf * 16 + q * 8 + (lane >> 2);
            float w = wsm[row];
            #pragma unroll
            for (int nf = 0; nf < 8; nf++) {
                int c0 = wn + nf * 8 + 2 * (lane & 3);
                thf[c0 * 128 + row]       = __float2half(acc[mf][nf][2 * q] * w);
                thf[(c0 + 1) * 128 + row] = __float2half(acc[mf][nf][2 * q + 1] * w);
            }
        }
    __syncthreads();

    for (int it = 0; it < 4; it++) {
        int idx = it * 512 + tid;
        int d = idx >> 3, mq = idx & 7;
        size_t go = ((size_t)br * DOUT + d) * Nn + n0 + mq * 16;
        *(uint4*)&g_wff[go]     = *(uint4*)&thf[d * 128 + mq * 16];
        *(uint4*)&g_wff[go + 8] = *(uint4*)&thf[d * 128 + mq * 16 + 8];
    }
}

// ---------------------------------------------------------------------------
// prepass: adj int32 -> fp16 {0,1}; invZ[br,n] = 1 / sum_m adj[n,m]*w[m]
// v2: 8 m-elems per lane-iter (2x int4 load -> 1x uint4 store), 4 iters/row
// ---------------------------------------------------------------------------
__global__ __launch_bounds__(256) void prepass_kernel(const int* __restrict__ adj) {
    __shared__ float ws[Nn];
    const int tid = threadIdx.x, wid = tid >> 5, lane = tid & 31;
    const int br = blockIdx.x >> 5, nb = blockIdx.x & 31;
    for (int i = tid; i < Nn; i += 256) ws[i] = g_w[br * Nn + i];
    __syncthreads();

    #pragma unroll
    for (int i = 0; i < 4; i++) {
        int n = nb * 32 + wid * 4 + i;
        const int4* arow = (const int4*)(adj + (((size_t)br << 10) + n) * Nn);
        __half* brow = g_adjh + (((size_t)br << 10) + n) * Nn;
        float z = 0.f;
        #pragma unroll
        for (int k = 0; k < 4; k++) {
            int m = k * 256 + lane * 8;
            int4 a0 = arow[k * 64 + lane * 2];
            int4 a1 = arow[k * 64 + lane * 2 + 1];
            uint4 o;
            o.x = (a0.x ? 0x3C00u : 0u) | ((a0.y ? 0x3C00u : 0u) << 16);
            o.y = (a0.z ? 0x3C00u : 0u) | ((a0.w ? 0x3C00u : 0u) << 16);
            o.z = (a1.x ? 0x3C00u : 0u) | ((a1.y ? 0x3C00u : 0u) << 16);
            o.w = (a1.z ? 0x3C00u : 0u) | ((a1.w ? 0x3C00u : 0u) << 16);
            *(uint4*)(brow + m) = o;
            if (a0.x) z += ws[m];
            if (a0.y) z += ws[m + 1];
            if (a0.z) z += ws[m + 2];
            if (a0.w) z += ws[m + 3];
            if (a1.x) z += ws[m + 4];
            if (a1.y) z += ws[m + 5];
            if (a1.z) z += ws[m + 6];
            if (a1.w) z += ws[m + 7];
        }
        #pragma unroll
        for (int o = 16; o; o >>= 1) z += __shfl_xor_sync(0xffffffffu, z, o);
        if (lane == 0) g_invZ[(br << 10) + n] = 1.0f / z;
    }
}

// ---------------------------------------------------------------------------
// agg via fp16 mma.sync [unchanged R8]:
//   out[b,n,d] = sum_r invZ[r,n] * (adj_r @ wf_r^T)[n,d]
// CTA tile 64n x 128d; 32 super-chunks of K=128 (2 sub-chunks of 64).
// 8 warps 2x4, warp tile 32n x 32d. grid (2, 16, 8) = 256 CTAs, 2 CTA/SM.
// ---------------------------------------------------------------------------
#define A_SMEM (1024 + 2 * 49152)
__global__ __launch_bounds__(256, 2) void agg_mma_kernel(float* __restrict__ out) {
    extern __shared__ char smem[];
    __shared__ float izs[Rr * 64];
    const uint32_t ab = (smem_u32(smem) + 1023) & ~1023u;
    const int tid = threadIdx.x, wid = tid >> 5, lane = tid & 31;
    const int d0 = blockIdx.x * 128;
    const int n0 = blockIdx.y * 64;
    const int b  = blockIdx.z;
    const int wm = (wid >> 2) * 32, wn = (wid & 3) * 32;

    if (tid < Rr * 64)
        izs[tid] = g_invZ[((b * Rr + (tid >> 6)) << 10) + n0 + (tid & 63)];

    auto prefetch = [&](int sc, int stage) {
        uint32_t sbase = ab + stage * 49152;
        #pragma unroll
        for (int cc = 0; cc < 2; cc++) {
            int c = sc * 2 + cc;
            int r = c >> 4, kc = c & 15, m0 = kc * 64;
            uint32_t base = sbase + cc * 24576;
            size_t brr = (size_t)(b * Rr + r);
            for (int u = tid; u < 1536; u += 256) {
                uint32_t dst;
                const __half* src;
                if (u < 512) {
                    int row = u >> 3, un = u & 7;
                    dst = base + sw128(row * 128 + un * 16);
                    src = g_adjh + (brr * Nn + n0 + row) * Nn + m0 + un * 8;
                } else {
                    int v = u - 512;
                    int row = v >> 3, un = v & 7;
                    dst = base + 8192 + sw128(row * 128 + un * 16);
                    src = g_wff + (brr * DOUT + d0 + row) * Nn + m0 + un * 8;
                }
                CP_ASYNC16(dst, (const char*)src);
            }
        }
        CP_COMMIT();
    };

    float total[2][4][4] = {};
    float acc[2][4][4] = {};
    const int grp = lane >> 3, l7 = lane & 7;
    const int arow = (grp & 1) * 8 + l7, ac16 = (grp >> 1) * 16;
    const int brow = (grp >> 1) * 8 + l7, bc16 = (grp & 1) * 16;
    const int SC = 32;

    prefetch(0, 0);
    for (int sc = 0; sc < SC; sc++) {
        if (sc + 1 < SC) { prefetch(sc + 1, (sc + 1) & 1); CP_WAIT1(); }
        else             { CP_WAIT0(); }
        __syncthreads();
        uint32_t sbase = ab + (sc & 1) * 49152;
        #pragma unroll
        for (int cc = 0; cc < 2; cc++) {
            uint32_t base = sbase + cc * 24576;
            #pragma unroll
            for (int ks = 0; ks < 4; ks++) {
                int kb = ks * 32;
                uint32_t A[2][4], Bf4[4][2];
                #pragma unroll
                for (int mf = 0; mf < 2; mf++) {
                    uint32_t off = sw128((wm + mf * 16 + arow) * 128 + kb + ac16);
                    ldsm4(A[mf][0], A[mf][1], A[mf][2], A[mf][3], base + off);
                }
                #pragma unroll
                for (int g = 0; g < 2; g++) {
                    uint32_t off = sw128((wn + g * 16 + brow) * 128 + kb + bc16);
                    uint32_t t0, t1, t2, t3;
                    ldsm4(t0, t1, t2, t3, base + 8192 + off);
                    Bf4[2*g][0] = t0; Bf4[2*g][1] = t1;
                    Bf4[2*g+1][0] = t2; Bf4[2*g+1][1] = t3;
                }
                #pragma unroll
                for (int mf = 0; mf < 2; mf++)
                    #pragma unroll
                    for (int nf = 0; nf < 4; nf++)
                        mma16816h(acc[mf][nf], A[mf], Bf4[nf]);
            }
        }
        __syncthreads();

        if ((sc & 7) == 7) {             // end of relation r: fold with invZ
            int r = sc >> 3;
            #pragma unroll
            for (int mf = 0; mf < 2; mf++) {
                float iz0 = izs[r * 64 + wm + mf * 16 + (lane >> 2)];
                float iz1 = izs[r * 64 + wm + mf * 16 + (lane >> 2) + 8];
                #pragma unroll
                for (int nf = 0; nf < 4; nf++) {
                    total[mf][nf][0] = fmaf(iz0, acc[mf][nf][0], total[mf][nf][0]);
                    total[mf][nf][1] = fmaf(iz0, acc[mf][nf][1], total[mf][nf][1]);
                    total[mf][nf][2] = fmaf(iz1, acc[mf][nf][2], total[mf][nf][2]);
                    total[mf][nf][3] = fmaf(iz1, acc[mf][nf][3], total[mf][nf][3]);
                    acc[mf][nf][0] = 0.f; acc[mf][nf][1] = 0.f;
                    acc[mf][nf][2] = 0.f; acc[mf][nf][3] = 0.f;
                }
            }
        }
    }

    #pragma unroll
    for (int nf = 0; nf < 4; nf++) {
        int col = d0 + wn + nf * 8 + 2 * (lane & 3);
        #pragma unroll
        for (int mf = 0; mf < 2; mf++) {
            int row = n0 + wm + mf * 16 + (lane >> 2);
            float* p0 = out + ((size_t)b * Nn + row) * DOUT + col;
            float* p1 = out + ((size_t)b * Nn + row + 8) * DOUT + col;
            p0[0] = total[mf][nf][0]; p0[1] = total[mf][nf][1];
            p1[0] = total[mf][nf][2]; p1[1] = total[mf][nf][3];
        }
    }
}

// ---------------------------------------------------------------------------
// gate epilogue: out = sigmoid(out . gw + gb) * out, one block per (b,n)
// ---------------------------------------------------------------------------
__global__ __launch_bounds__(256) void gate_kernel(
    float* __restrict__ out, const float* __restrict__ gw,
    const float* __restrict__ gb_p)
{
    __shared__ float red[8];
    float* o = out + (size_t)blockIdx.x * DOUT;
    int t = threadIdx.x, lane = t & 31;
    float a = o[t];
    float v = a * gw[t];
    #pragma unroll
    for (int off = 16; off; off >>= 1) v += __shfl_xor_sync(0xffffffffu, v, off);
    if (lane == 0) red[t >> 5] = v;
    __syncthreads();
    if (t < 32) {
        float r = (t < 8) ? red[t] : 0.0f;
        #pragma unroll
        for (int off = 4; off; off >>= 1) r += __shfl_xor_sync(0xffffffffu, r, off);
        if (t == 0) red[0] = r;
    }
    __syncthreads();
    float g = 1.0f / (1.0f + __expf(-(red[0] + gb_p[0])));
    o[t] = g * a;
}

// ---------------------------------------------------------------------------
extern "C" void kernel_launch(void* const* d_in, const int* in_sizes, int n_in,
                              void* d_out, int out_size)
{
    const float* x   = (const float*)d_in[0];
    const int*   adj = (const int*)  d_in[1];
    const float* rw  = (const float*)d_in[2];
    const float* rb  = (const float*)d_in[3];
    const float* aw  = (const float*)d_in[4];
    const float* gw  = (const float*)d_in[6];
    const float* gb  = (const float*)d_in[7];
    float* out = (float*)d_out;

    static bool init_done = false;
    if (!init_done) {
        cudaFuncSetAttribute(fw_kernel,
                             cudaFuncAttributeMaxDynamicSharedMemorySize, FW_SMEM);
        cudaFuncSetAttribute(agg_mma_kernel,
                             cudaFuncAttributeMaxDynamicSharedMemorySize, A_SMEM);
        init_done = true;
    }

    conv_x_kernel<<<(Bq * Nn * DIN / 4) / 256, 256>>>(x);
    conv_rw_kernel<<<(Rr * DOUT * DIN / 4) / 256, 256>>>(rw);

    fw_kernel<<<dim3(8, Bq * Rr), 512, FW_SMEM>>>(rb, aw);

    prepass_kernel<<<Bq * Rr * 32, 256>>>(adj);

    agg_mma_kernel<<<dim3(2, 16, Bq), 256, A_SMEM>>>(out);

    gate_kernel<<<Bq * Nn, 256>>>(out, gw, gb);
}

// round 14
// speedup vs baseline: 1.5876x; 1.0702x over previous
#include <cuda_runtime.h>
#include <cuda_fp16.h>
#include <cstdint>

#define Bq   8
#define Nn   1024
#define DIN  256
#define DOUT 256
#define Rr   4

// ------------------------- scratch globals ----------------------------------
__device__ __half g_xf[(size_t)Bq * Nn * DIN];
__device__ __half g_rwhf[(size_t)Rr * DOUT * DIN];
__device__ __half g_rwlf[(size_t)Rr * DOUT * DIN];
__device__ float  g_w[Bq * Rr * Nn];
__device__ float  g_invZ[Bq * Rr * Nn];
__device__ __half g_wff[(size_t)Bq * Rr * DOUT * Nn];      // wf^T fp16 [br][d][m]
__device__ __half g_adjh[(size_t)Bq * Rr * Nn * Nn];       // 64 MB fp16 {0,1}

// ------------------------- helpers ------------------------------------------
__device__ __forceinline__ uint32_t smem_u32(const void* p) {
    uint32_t a;
    asm("{ .reg .u64 t; cvta.to.shared.u64 t, %1; cvt.u32.u64 %0, t; }"
        : "=r"(a) : "l"(p));
    return a;
}
#define CP_ASYNC16(dst, src) asm volatile("cp.async.cg.shared.global [%0], [%1], 16;" :: "r"(dst), "l"(src))
#define CP_COMMIT()          asm volatile("cp.async.commit_group;" ::: "memory")
#define CP_WAIT1()           asm volatile("cp.async.wait_group 1;" ::: "memory")
#define CP_WAIT0()           asm volatile("cp.async.wait_group 0;" ::: "memory")

__device__ __forceinline__ uint32_t sw128(uint32_t off) {
    return off ^ ((off >> 3) & 0x70);
}
__device__ __forceinline__ void ldsm4(uint32_t& r0, uint32_t& r1,
                                      uint32_t& r2, uint32_t& r3, uint32_t a) {
    asm volatile("ldmatrix.sync.aligned.m8n8.x4.shared.b16 {%0,%1,%2,%3}, [%4];"
                 : "=r"(r0), "=r"(r1), "=r"(r2), "=r"(r3) : "r"(a));
}
__device__ __forceinline__ void mma16816h(float* c, const uint32_t* a,
                                          const uint32_t* b) {
    asm volatile("mma.sync.aligned.m16n8k16.row.col.f32.f16.f16.f32 "
        "{%0,%1,%2,%3}, {%4,%5,%6,%7}, {%8,%9}, {%0,%1,%2,%3};"
        : "+f"(c[0]), "+f"(c[1]), "+f"(c[2]), "+f"(c[3])
        : "r"(a[0]), "r"(a[1]), "r"(a[2]), "r"(a[3]), "r"(b[0]), "r"(b[1]));
}
__device__ __forceinline__ void hsplit(float v, __half& h, __half& l) {
    h = __float2half_rn(v);
    l = __float2half_rn(v - __half2float(h));
}
__device__ __forceinline__ uint32_t pack_h2(__half a, __half b) {
    return (uint32_t)__half_as_ushort(a) | ((uint32_t)__half_as_ushort(b) << 16);
}

// ---------------------------------------------------------------------------
// merged conversions: blocks [0, XB) convert x (single fp16);
//                     blocks [XB, XB+WB) convert rel_w (hi/lo fp16)
// ---------------------------------------------------------------------------
#define XB ((Bq * Nn * DIN / 4) / 256)
#define WB ((Rr * DOUT * DIN / 4) / 256)
__global__ __launch_bounds__(256) void conv_kernel(const float* __restrict__ x,
                                                   const float* __restrict__ rw) {
    if (blockIdx.x < XB) {
        size_t i = (size_t)blockIdx.x * 256 + threadIdx.x;
        float4 v = ((const float4*)x)[i];
        uint2 H;
        H.x = pack_h2(__float2half_rn(v.x), __float2half_rn(v.y));
        H.y = pack_h2(__float2half_rn(v.z), __float2half_rn(v.w));
        *(uint2*)&g_xf[4 * i] = H;
    } else {
        size_t i = (size_t)(blockIdx.x - XB) * 256 + threadIdx.x;
        float4 v = ((const float4*)rw)[i];
        __half h0, h1, h2, h3, l0, l1, l2, l3;
        hsplit(v.x, h0, l0); hsplit(v.y, h1, l1);
        hsplit(v.z, h2, l2); hsplit(v.w, h3, l3);
        uint2 H, L;
        H.x = pack_h2(h0, h1); H.y = pack_h2(h2, h3);
        L.x = pack_h2(l0, l1); L.y = pack_h2(l2, l3);
        *(uint2*)&g_rwhf[4 * i] = H;
        *(uint2*)&g_rwlf[4 * i] = L;
    }
}

// ---------------------------------------------------------------------------
// FUSED feats+wf kernel (2-term fp16: x single, rw hi/lo)  [byte-exact R8]
// ---------------------------------------------------------------------------
#define FW_SMEM (1024 + 2 * 81920)
__global__ __launch_bounds__(512, 1) void fw_kernel(
    const float* __restrict__ rb, const float* __restrict__ aw)
{
    extern __shared__ char smem[];
    __shared__ float awjs[256];
    __shared__ float rbs[256];
    __shared__ float sjred[4][128];
    __shared__ float wsm[128];
    char* abp = (char*)(((uintptr_t)smem + 1023) & ~(uintptr_t)1023);
    const uint32_t ab = (smem_u32(smem) + 1023) & ~1023u;
    const int tid = threadIdx.x, wid = tid >> 5, lane = tid & 31;
    const int n0 = blockIdx.x * 128;
    const int br = blockIdx.y, b = br >> 2, r = br & 3;
    const int wm = (wid >> 2) * 32, wn = (wid & 3) * 64;

    if (tid < 256) { awjs[tid] = aw[DOUT + tid]; rbs[tid] = rb[r * DOUT + tid]; }

    auto prefetch = [&](int c, int stage) {
        uint32_t base = ab + stage * 81920;
        for (int u = tid; u < 5120; u += 512) {
            uint32_t dst;
            const __half* src;
            if (u < 1024) {
                int row = u >> 3, un = u & 7;
                dst = base + sw128(row * 128 + un * 16);
                src = g_xf + (size_t)b * (Nn * DIN) + (size_t)(n0 + row) * DIN
                    + c * 64 + un * 8;
            } else {
                int v2 = u - 1024;
                int t = v2 >> 11, v = v2 & 2047, row = v >> 3, un = v & 7;
                dst = base + 16384 + t * 32768 + sw128(row * 128 + un * 16);
                src = (t ? g_rwlf : g_rwhf)
                    + (size_t)r * (DOUT * DIN) + (size_t)row * DIN + c * 64 + un * 8;
            }
            CP_ASYNC16(dst, (const char*)src);
        }
        CP_COMMIT();
    };

    float acc[2][8][4] = {};
    const int grp = lane >> 3, l7 = lane & 7;
    const int arow = (grp & 1) * 8 + l7, ac16 = (grp >> 1) * 16;
    const int brow = (grp >> 1) * 8 + l7, bc16 = (grp & 1) * 16;

    prefetch(0, 0);
    for (int c = 0; c < 4; c++) {
        if (c + 1 < 4) { prefetch(c + 1, (c + 1) & 1); CP_WAIT1(); }
        else           { CP_WAIT0(); }
        __syncthreads();
        uint32_t base = ab + (c & 1) * 81920;
        #pragma unroll
        for (int ks = 0; ks < 4; ks++) {
            int kb = ks * 32;
            uint32_t Ax[2][4];
            #pragma unroll
            for (int mf = 0; mf < 2; mf++) {
                uint32_t off = sw128((wm + mf * 16 + arow) * 128 + kb + ac16);
                ldsm4(Ax[mf][0], Ax[mf][1], Ax[mf][2], Ax[mf][3], base + off);
            }
            #pragma unroll
            for (int g = 0; g < 4; g++) {
                uint32_t off = sw128((wn + g * 16 + brow) * 128 + kb + bc16);
                uint32_t h0, h1, h2, h3, q0, q1, q2, q3;
                ldsm4(h0, h1, h2, h3, base + 16384 + off);
                ldsm4(q0, q1, q2, q3, base + 49152 + off);
                uint32_t Bh0[2] = {h0, h1}, Bh1[2] = {h2, h3};
                uint32_t Bl0[2] = {q0, q1}, Bl1[2] = {q2, q3};
                #pragma unroll
                for (int mf = 0; mf < 2; mf++) {
                    mma16816h(acc[mf][2*g],   Ax[mf], Bh0);
                    mma16816h(acc[mf][2*g+1], Ax[mf], Bh1);
                    mma16816h(acc[mf][2*g],   Ax[mf], Bl0);
                    mma16816h(acc[mf][2*g+1], Ax[mf], Bl1);
                }
            }
        }
        __syncthreads();
    }

    #pragma unroll
    for (int nf = 0; nf < 8; nf++) {
        int c0 = wn + nf * 8 + 2 * (lane & 3);
        float b0 = rbs[c0], b1 = rbs[c0 + 1];
        #pragma unroll
        for (int mf = 0; mf < 2; mf++) {
            acc[mf][nf][0] += b0; acc[mf][nf][1] += b1;
            acc[mf][nf][2] += b0; acc[mf][nf][3] += b1;
        }
    }

    float p[2][2] = {};
    #pragma unroll
    for (int nf = 0; nf < 8; nf++) {
        int c0 = wn + nf * 8 + 2 * (lane & 3);
        float a0 = awjs[c0], a1 = awjs[c0 + 1];
        #pragma unroll
        for (int mf = 0; mf < 2; mf++) {
            p[mf][0] = fmaf(acc[mf][nf][0], a0, fmaf(acc[mf][nf][1], a1, p[mf][0]));
            p[mf][1] = fmaf(acc[mf][nf][2], a0, fmaf(acc[mf][nf][3], a1, p[mf][1]));
        }
    }
    #pragma unroll
    for (int mf = 0; mf < 2; mf++)
        #pragma unroll
        for (int q = 0; q < 2; q++) {
            p[mf][q] += __shfl_xor_sync(0xffffffffu, p[mf][q], 1);
            p[mf][q] += __shfl_xor_sync(0xffffffffu, p[mf][q], 2);
            if ((lane & 3) == 0)
                sjred[wid & 3][wm + mf * 16 + q * 8 + (lane >> 2)] = p[mf][q];
        }
    __syncthreads();

    if (tid < 128) {
        float s = sjred[0][tid] + sjred[1][tid] + sjred[2][tid] + sjred[3][tid];
        float w = __expf(s);
        wsm[tid] = w;
        g_w[br * Nn + n0 + tid] = w;
    }
    __syncthreads();

    __half* thf = (__half*)abp;
    #pragma unroll
    for (int mf = 0; mf < 2; mf++)
        #pragma unroll
        for (int q = 0; q < 2; q++) {
            int row = wm + mf * 16 + q * 8 + (lane >> 2);
            float w = wsm[row];
            #pragma unroll
            for (int nf = 0; nf < 8; nf++) {
                int c0 = wn + nf * 8 + 2 * (lane & 3);
                thf[c0 * 128 + row]       = __float2half(acc[mf][nf][2 * q] * w);
                thf[(c0 + 1) * 128 + row] = __float2half(acc[mf][nf][2 * q + 1] * w);
            }
        }
    __syncthreads();

    for (int it = 0; it < 4; it++) {
        int idx = it * 512 + tid;
        int d = idx >> 3, mq = idx & 7;
        size_t go = ((size_t)br * DOUT + d) * Nn + n0 + mq * 16;
        *(uint4*)&g_wff[go]     = *(uint4*)&thf[d * 128 + mq * 16];
        *(uint4*)&g_wff[go + 8] = *(uint4*)&thf[d * 128 + mq * 16 + 8];
    }
}

// ---------------------------------------------------------------------------
// prepass: adj int32 -> fp16 {0,1}; invZ = 1/sum adj*w   [byte-exact R8]
// ---------------------------------------------------------------------------
__global__ __launch_bounds__(256) void prepass_kernel(const int* __restrict__ adj) {
    __shared__ float ws[Nn];
    const int tid = threadIdx.x, wid = tid >> 5, lane = tid & 31;
    const int br = blockIdx.x >> 5, nb = blockIdx.x & 31;
    for (int i = tid; i < Nn; i += 256) ws[i] = g_w[br * Nn + i];
    __syncthreads();

    #pragma unroll
    for (int i = 0; i < 4; i++) {
        int n = nb * 32 + wid * 4 + i;
        const int4* arow = (const int4*)(adj + (((size_t)br << 10) + n) * Nn);
        __half* brow = g_adjh + (((size_t)br << 10) + n) * Nn;
        float z = 0.f;
        #pragma unroll
        for (int k = 0; k < 8; k++) {
            int m = k * 128 + lane * 4;
            int4 a = arow[k * 32 + lane];
            uint2 o;
            o.x = (a.x ? 0x3C00u : 0u) | ((a.y ? 0x3C00u : 0u) << 16);
            o.y = (a.z ? 0x3C00u : 0u) | ((a.w ? 0x3C00u : 0u) << 16);
            *(uint2*)(brow + m) = o;
            if (a.x) z += ws[m];
            if (a.y) z += ws[m + 1];
            if (a.z) z += ws[m + 2];
            if (a.w) z += ws[m + 3];
        }
        #pragma unroll
        for (int o = 16; o; o >>= 1) z += __shfl_xor_sync(0xffffffffu, z, o);
        if (lane == 0) g_invZ[(br << 10) + n] = 1.0f / z;
    }
}

// ---------------------------------------------------------------------------
// agg via fp16 mma.sync [byte-exact R8]:
//   out[b,n,d] = sum_r invZ[r,n] * (adj_r @ wf_r^T)[n,d]
// CTA tile 64n x 128d; 32 super-chunks of K=128 (2 sub-chunks of 64).
// 8 warps 2x4, warp tile 32n x 32d. grid (2, 16, 8) = 256 CTAs, 2 CTA/SM.
// ---------------------------------------------------------------------------
#define A_SMEM (1024 + 2 * 49152)
__global__ __launch_bounds__(256, 2) void agg_mma_kernel(float* __restrict__ out) {
    extern __shared__ char smem[];
    __shared__ float izs[Rr * 64];
    const uint32_t ab = (smem_u32(smem) + 1023) & ~1023u;
    const int tid = threadIdx.x, wid = tid >> 5, lane = tid & 31;
    const int d0 = blockIdx.x * 128;
    const int n0 = blockIdx.y * 64;
    const int b  = blockIdx.z;
    const int wm = (wid >> 2) * 32, wn = (wid & 3) * 32;

    if (tid < Rr * 64)
        izs[tid] = g_invZ[((b * Rr + (tid >> 6)) << 10) + n0 + (tid & 63)];

    auto prefetch = [&](int sc, int stage) {
        uint32_t sbase = ab + stage * 49152;
        #pragma unroll
        for (int cc = 0; cc < 2; cc++) {
            int c = sc * 2 + cc;
            int r = c >> 4, kc = c & 15, m0 = kc * 64;
            uint32_t base = sbase + cc * 24576;
            size_t brr = (size_t)(b * Rr + r);
            for (int u = tid; u < 1536; u += 256) {
                uint32_t dst;
                const __half* src;
                if (u < 512) {
                    int row = u >> 3, un = u & 7;
                    dst = base + sw128(row * 128 + un * 16);
                    src = g_adjh + (brr * Nn + n0 + row) * Nn + m0 + un * 8;
                } else {
                    int v = u - 512;
                    int row = v >> 3, un = v & 7;
                    dst = base + 8192 + sw128(row * 128 + un * 16);
                    src = g_wff + (brr * DOUT + d0 + row) * Nn + m0 + un * 8;
                }
                CP_ASYNC16(dst, (const char*)src);
            }
        }
        CP_COMMIT();
    };

    float total[2][4][4] = {};
    float acc[2][4][4] = {};
    const int grp = lane >> 3, l7 = lane & 7;
    const int arow = (grp & 1) * 8 + l7, ac16 = (grp >> 1) * 16;
    const int brow = (grp >> 1) * 8 + l7, bc16 = (grp & 1) * 16;
    const int SC = 32;

    prefetch(0, 0);
    for (int sc = 0; sc < SC; sc++) {
        if (sc + 1 < SC) { prefetch(sc + 1, (sc + 1) & 1); CP_WAIT1(); }
        else             { CP_WAIT0(); }
        __syncthreads();
        uint32_t sbase = ab + (sc & 1) * 49152;
        #pragma unroll
        for (int cc = 0; cc < 2; cc++) {
            uint32_t base = sbase + cc * 24576;
            #pragma unroll
            for (int ks = 0; ks < 4; ks++) {
                int kb = ks * 32;
                uint32_t A[2][4], Bf4[4][2];
                #pragma unroll
                for (int mf = 0; mf < 2; mf++) {
                    uint32_t off = sw128((wm + mf * 16 + arow) * 128 + kb + ac16);
                    ldsm4(A[mf][0], A[mf][1], A[mf][2], A[mf][3], base + off);
                }
                #pragma unroll
                for (int g = 0; g < 2; g++) {
                    uint32_t off = sw128((wn + g * 16 + brow) * 128 + kb + bc16);
                    uint32_t t0, t1, t2, t3;
                    ldsm4(t0, t1, t2, t3, base + 8192 + off);
                    Bf4[2*g][0] = t0; Bf4[2*g][1] = t1;
                    Bf4[2*g+1][0] = t2; Bf4[2*g+1][1] = t3;
                }
                #pragma unroll
                for (int mf = 0; mf < 2; mf++)
                    #pragma unroll
                    for (int nf = 0; nf < 4; nf++)
                        mma16816h(acc[mf][nf], A[mf], Bf4[nf]);
            }
        }
        __syncthreads();

        if ((sc & 7) == 7) {             // end of relation r: fold with invZ
            int r = sc >> 3;
            #pragma unroll
            for (int mf = 0; mf < 2; mf++) {
                float iz0 = izs[r * 64 + wm + mf * 16 + (lane >> 2)];
                float iz1 = izs[r * 64 + wm + mf * 16 + (lane >> 2) + 8];
                #pragma unroll
                for (int nf = 0; nf < 4; nf++) {
                    total[mf][nf][0] = fmaf(iz0, acc[mf][nf][0], total[mf][nf][0]);
                    total[mf][nf][1] = fmaf(iz0, acc[mf][nf][1], total[mf][nf][1]);
                    total[mf][nf][2] = fmaf(iz1, acc[mf][nf][2], total[mf][nf][2]);
                    total[mf][nf][3] = fmaf(iz1, acc[mf][nf][3], total[mf][nf][3]);
                    acc[mf][nf][0] = 0.f; acc[mf][nf][1] = 0.f;
                    acc[mf][nf][2] = 0.f; acc[mf][nf][3] = 0.f;
                }
            }
        }
    }

    #pragma unroll
    for (int nf = 0; nf < 4; nf++) {
        int col = d0 + wn + nf * 8 + 2 * (lane & 3);
        #pragma unroll
        for (int mf = 0; mf < 2; mf++) {
            int row = n0 + wm + mf * 16 + (lane >> 2);
            float* p0 = out + ((size_t)b * Nn + row) * DOUT + col;
            float* p1 = out + ((size_t)b * Nn + row + 8) * DOUT + col;
            p0[0] = total[mf][nf][0]; p0[1] = total[mf][nf][1];
            p1[0] = total[mf][nf][2]; p1[1] = total[mf][nf][3];
        }
    }
}

// ---------------------------------------------------------------------------
// gate v2: warp-per-row, no block barriers.
// row dot: lane covers cols {lane*4..+4} and {128+lane*4..+4}; shfl reduce.
// grid = Bq*Nn/8 = 1024 blocks, 256 threads (8 warps = 8 rows).
// ---------------------------------------------------------------------------
__global__ __launch_bounds__(256) void gate_kernel(
    float* __restrict__ out, const float* __restrict__ gw,
    const float* __restrict__ gb_p)
{
    const int wid = threadIdx.x >> 5, lane = threadIdx.x & 31;
    const size_t row = (size_t)blockIdx.x * 8 + wid;
    float* o = out + row * DOUT;

    float4 a0 = *(const float4*)(o + lane * 4);
    float4 a1 = *(const float4*)(o + 128 + lane * 4);
    float4 w0 = __ldg((const float4*)(gw + lane * 4));
    float4 w1 = __ldg((const float4*)(gw + 128 + lane * 4));

    float s = a0.x * w0.x + a0.y * w0.y + a0.z * w0.z + a0.w * w0.w
            + a1.x * w1.x + a1.y * w1.y + a1.z * w1.z + a1.w * w1.w;
    #pragma unroll
    for (int off = 16; off; off >>= 1) s += __shfl_xor_sync(0xffffffffu, s, off);

    float g = 1.0f / (1.0f + __expf(-(s + gb_p[0])));
    a0.x *= g; a0.y *= g; a0.z *= g; a0.w *= g;
    a1.x *= g; a1.y *= g; a1.z *= g; a1.w *= g;
    *(float4*)(o + lane * 4) = a0;
    *(float4*)(o + 128 + lane * 4) = a1;
}

// ---------------------------------------------------------------------------
extern "C" void kernel_launch(void* const* d_in, const int* in_sizes, int n_in,
                              void* d_out, int out_size)
{
    const float* x   = (const float*)d_in[0];
    const int*   adj = (const int*)  d_in[1];
    const float* rw  = (const float*)d_in[2];
    const float* rb  = (const float*)d_in[3];
    const float* aw  = (const float*)d_in[4];
    const float* gw  = (const float*)d_in[6];
    const float* gb  = (const float*)d_in[7];
    float* out = (float*)d_out;

    static bool init_done = false;
    if (!init_done) {
        cudaFuncSetAttribute(fw_kernel,
                             cudaFuncAttributeMaxDynamicSharedMemorySize, FW_SMEM);
        cudaFuncSetAttribute(agg_mma_kernel,
                             cudaFuncAttributeMaxDynamicSharedMemorySize, A_SMEM);
        init_done = true;
    }

    conv_kernel<<<XB + WB, 256>>>(x, rw);

    fw_kernel<<<dim3(8, Bq * Rr), 512, FW_SMEM>>>(rb, aw);

    prepass_kernel<<<Bq * Rr * 32, 256>>>(adj);

    agg_mma_kernel<<<dim3(2, 16, Bq), 256, A_SMEM>>>(out);

    gate_kernel<<<(Bq * Nn) / 8, 256>>>(out, gw, gb);
}